// round 9
// baseline (speedup 1.0000x reference)
#include <cuda_runtime.h>
#include <mma.h>

using namespace nvcuda;

#define NN 100000
#define NE 1600000
#define D 48
#define NCONVS 6
#define NG 1000

#define EPC 128     // edges per CTA for wmma edge kernel

#define SCAN_BLK 1024
#define NSCAN_BLKS ((NN + SCAN_BLK - 1) / SCAN_BLK)   // 98

typedef unsigned long long u64;
typedef unsigned int u32;

// Scratch state (no allocation allowed).
__device__ float4 g_h[NN * 12];
__device__ float4 g_agg[NN * 12];
// counting-sort scratch
__device__ int g_cnt[NN];
__device__ int g_scan[NN];
__device__ int g_bsum[NSCAN_BLKS];
__device__ int g_woff[NN];
__device__ int g_ssrc[NE];
__device__ int g_sdst[NE];

// ---------- helpers ----------
__device__ __forceinline__ u64 fma2(u64 a, u64 b, u64 c) {
    u64 d;
    asm("fma.rn.f32x2 %0, %1, %2, %3;" : "=l"(d) : "l"(a), "l"(b), "l"(c));
    return d;
}
__device__ __forceinline__ u64 pack2(float lo, float hi) {
    u64 r;
    asm("mov.b64 %0, {%1, %2};" : "=l"(r) : "f"(lo), "f"(hi));
    return r;
}
__device__ __forceinline__ float2 unpack2(u64 v) {
    float2 f;
    asm("mov.b64 {%0, %1}, %2;" : "=f"(f.x), "=f"(f.y) : "l"(v));
    return f;
}
__device__ __forceinline__ float f2tf32(float x) {
    u32 r;
    asm("cvt.rn.tf32.f32 %0, %1;" : "=r"(r) : "f"(x));
    return __uint_as_float(r);
}

// ---------- counting sort by dst ----------
__global__ void zero_cnt_kernel() {
    int i = blockIdx.x * blockDim.x + threadIdx.x;
    if (i < NN) g_cnt[i] = 0;
}
__global__ void hist_kernel(const int* __restrict__ edge) {
    int e = blockIdx.x * blockDim.x + threadIdx.x;
    if (e < NE) atomicAdd(&g_cnt[edge[NE + e]], 1);
}
__global__ void scan1_kernel() {
    __shared__ int sh[SCAN_BLK];
    int tid = threadIdx.x;
    int i = blockIdx.x * SCAN_BLK + tid;
    int v = (i < NN) ? g_cnt[i] : 0;
    sh[tid] = v;
    __syncthreads();
#pragma unroll
    for (int o = 1; o < SCAN_BLK; o <<= 1) {
        int t = (tid >= o) ? sh[tid - o] : 0;
        __syncthreads();
        sh[tid] += t;
        __syncthreads();
    }
    if (i < NN) g_scan[i] = sh[tid];
    if (tid == SCAN_BLK - 1) g_bsum[blockIdx.x] = sh[tid];
}
__global__ void scan2_kernel() {
    if (threadIdx.x == 0 && blockIdx.x == 0) {
        int acc = 0;
        for (int b = 0; b < NSCAN_BLKS; b++) {
            int t = g_bsum[b];
            g_bsum[b] = acc;
            acc += t;
        }
    }
}
__global__ void scan3_kernel() {
    int i = blockIdx.x * blockDim.x + threadIdx.x;
    if (i < NN) g_woff[i] = g_scan[i] - g_cnt[i] + g_bsum[i / SCAN_BLK];
}
__global__ void scatter_sort_kernel(const int* __restrict__ edge) {
    int e = blockIdx.x * blockDim.x + threadIdx.x;
    if (e >= NE) return;
    int d = edge[NE + e];
    int pos = atomicAdd(&g_woff[d], 1);
    g_ssrc[pos] = edge[e];
    g_sdst[pos] = d;
}

// ---------- WMMA edge kernel ----------
// SMEM layout (floats):
#define OFF_AH   0                      // 128x48 tf32-hi of x (row-major, ld 48)
#define OFF_AL   6144                   // 128x48 tf32-lo
#define OFF_W1H  12288                  // 48x48
#define OFF_W1L  14592
#define OFF_W2H  16896
#define OFF_W2L  19200
#define OFF_HID  21504                  // 128x48 f32 GEMM output staging
#define OFF_B1   27648                  // 48
#define OFF_B2   27696                  // 48
#define EDGE_SMEM_FLOATS 27744          // 110976 bytes

__global__ __launch_bounds__(128, 2) void edge_wmma_kernel(
    const float* __restrict__ w1, const float* __restrict__ b1,
    const float* __restrict__ w2, const float* __restrict__ b2, int layer) {
    extern __shared__ __align__(16) float s[];
    int tid = threadIdx.x;
    int warp = tid >> 5;
    int e_base = blockIdx.x * EPC;

    // ---- load + split weights (tf32 hi/lo) ----
    const float* w1g = w1 + layer * D * D;
    const float* w2g = w2 + layer * D * D;
#pragma unroll
    for (int i = tid; i < D * D; i += 128) {
        float v1 = w1g[i];
        float h1 = f2tf32(v1);
        s[OFF_W1H + i] = h1;
        s[OFF_W1L + i] = f2tf32(v1 - h1);
        float v2 = w2g[i];
        float h2 = f2tf32(v2);
        s[OFF_W2H + i] = h2;
        s[OFF_W2L + i] = f2tf32(v2 - h2);
    }
    if (tid < D) {
        s[OFF_B1 + tid] = b1[layer * D + tid];
        s[OFF_B2 + tid] = b2[layer * D + tid];
    }

    // ---- cooperative gather: x = h[src]*h[dst], split into AH/AL ----
#pragma unroll
    for (int it = 0; it < 4; it++) {
        int idx = it * 128 + tid;      // 0..511
        int el = idx >> 2;             // local edge 0..127
        int ch = idx & 3;              // chunk 0..3 (12 floats each)
        int e = e_base + el;
        int sn = g_ssrc[e];
        int dn = g_sdst[e];
        const float4* hs = (const float4*)&g_h[sn * 12] + ch * 3;
        const float4* hd = (const float4*)&g_h[dn * 12] + ch * 3;
        float* ah = s + OFF_AH + el * D + ch * 12;
        float* al = s + OFF_AL + el * D + ch * 12;
#pragma unroll
        for (int i = 0; i < 3; i++) {
            float4 a = hs[i];
            float4 b = hd[i];
            float p0 = a.x * b.x, p1 = a.y * b.y, p2 = a.z * b.z, p3 = a.w * b.w;
            float h0 = f2tf32(p0), h1 = f2tf32(p1), h2 = f2tf32(p2), h3 = f2tf32(p3);
            ah[4 * i + 0] = h0; al[4 * i + 0] = f2tf32(p0 - h0);
            ah[4 * i + 1] = h1; al[4 * i + 1] = f2tf32(p1 - h1);
            ah[4 * i + 2] = h2; al[4 * i + 2] = f2tf32(p2 - h2);
            ah[4 * i + 3] = h3; al[4 * i + 3] = f2tf32(p3 - h3);
        }
    }
    __syncthreads();

    // ---- GEMM helper (lambda-like macro via loop): C[128x48] = A3term @ W ----
    // Each warp: 2 M-tiles (16 rows) x 3 N-tiles.
#define DO_GEMM(WH_OFF, WL_OFF)                                                        \
    for (int mti = 0; mti < 2; mti++) {                                                \
        int mt = 2 * warp + mti;                                                       \
        wmma::fragment<wmma::accumulator, 16, 16, 8, float> acc[3];                    \
        wmma::fill_fragment(acc[0], 0.0f);                                             \
        wmma::fill_fragment(acc[1], 0.0f);                                             \
        wmma::fill_fragment(acc[2], 0.0f);                                             \
        for (int term = 0; term < 3; term++) {                                         \
            const float* Abuf = s + ((term == 1) ? OFF_AL : OFF_AH);                   \
            const float* Wbuf = s + ((term == 2) ? (WL_OFF) : (WH_OFF));               \
            for (int k = 0; k < 6; k++) {                                              \
                wmma::fragment<wmma::matrix_a, 16, 16, 8, wmma::precision::tf32,       \
                               wmma::row_major> af;                                    \
                wmma::load_matrix_sync(af, Abuf + (mt * 16) * D + k * 8, D);           \
                for (int nt = 0; nt < 3; nt++) {                                       \
                    wmma::fragment<wmma::matrix_b, 16, 16, 8, wmma::precision::tf32,   \
                                   wmma::row_major> bf;                                \
                    wmma::load_matrix_sync(bf, Wbuf + (k * 8) * D + nt * 16, D);       \
                    wmma::mma_sync(acc[nt], af, bf, acc[nt]);                          \
                }                                                                      \
            }                                                                          \
        }                                                                              \
        for (int nt = 0; nt < 3; nt++)                                                 \
            wmma::store_matrix_sync(s + OFF_HID + (mt * 16) * D + nt * 16, acc[nt],    \
                                    D, wmma::mem_row_major);                           \
    }

    // ---- GEMM1 ----
    DO_GEMM(OFF_W1H, OFF_W1L)
    __syncthreads();

    // ---- relu(hid + b1), split back into AH/AL ----
    {
        const float* hid = s + OFF_HID + tid * D;
        float* ah = s + OFF_AH + tid * D;
        float* al = s + OFF_AL + tid * D;
#pragma unroll
        for (int j = 0; j < D; j++) {
            float v = fmaxf(hid[j] + s[OFF_B1 + j], 0.f);
            float h = f2tf32(v);
            ah[j] = h;
            al[j] = f2tf32(v - h);
        }
    }
    __syncthreads();

    // ---- GEMM2 ----
    DO_GEMM(OFF_W2H, OFF_W2L)
    __syncthreads();

    // ---- epilogue: m = hid + b2 ; red.v4 scatter into g_agg[dst] ----
#pragma unroll
    for (int it = 0; it < 4; it++) {
        int idx = it * 128 + tid;
        int el = idx >> 2;
        int ch = idx & 3;
        int dn = g_sdst[e_base + el];
        const float* hid = s + OFF_HID + el * D + ch * 12;
        const float* b2s = s + OFF_B2 + ch * 12;
        float* aggp = (float*)&g_agg[dn * 12] + ch * 12;
#pragma unroll
        for (int i = 0; i < 3; i++) {
            float m0 = hid[4 * i + 0] + b2s[4 * i + 0];
            float m1 = hid[4 * i + 1] + b2s[4 * i + 1];
            float m2 = hid[4 * i + 2] + b2s[4 * i + 2];
            float m3 = hid[4 * i + 3] + b2s[4 * i + 3];
            asm volatile("red.global.add.v4.f32 [%0], {%1, %2, %3, %4};"
                         :: "l"(aggp + 4 * i), "f"(m0), "f"(m1), "f"(m2), "f"(m3) : "memory");
        }
    }
}

// ---------- scalar GEMM helpers (update / readout) ----------
__device__ __forceinline__ void gemm48_half(const float x[D], u64 acc[12],
                                            const float* __restrict__ ws,
                                            const float* __restrict__ bs) {
#pragma unroll
    for (int j = 0; j < 12; j++) acc[j] = *(const u64*)(bs + 2 * j);
#pragma unroll 4
    for (int k = 0; k < D; k++) {
        u64 xk = pack2(x[k], x[k]);
        const ulonglong2* wr = (const ulonglong2*)(ws + k * D);
#pragma unroll
        for (int jj = 0; jj < 6; jj++) {
            ulonglong2 w = wr[jj];
            acc[2 * jj]     = fma2(xk, w.x, acc[2 * jj]);
            acc[2 * jj + 1] = fma2(xk, w.y, acc[2 * jj + 1]);
        }
    }
}

__device__ __forceinline__ void mlp2_48(const float x[D], float out[D],
                                        const float* __restrict__ w1s, const float* __restrict__ b1s,
                                        const float* __restrict__ w2s, const float* __restrict__ b2s) {
    float hid[D];
#pragma unroll 1
    for (int half = 0; half < 2; half++) {
        u64 acc[12];
        gemm48_half(x, acc, w1s + half * 24, b1s + half * 24);
#pragma unroll
        for (int j = 0; j < 12; j++) {
            float2 v = unpack2(acc[j]);
            hid[half * 24 + 2 * j]     = fmaxf(v.x, 0.f);
            hid[half * 24 + 2 * j + 1] = fmaxf(v.y, 0.f);
        }
    }
#pragma unroll 1
    for (int half = 0; half < 2; half++) {
        u64 acc[12];
        gemm48_half(hid, acc, w2s + half * 24, b2s + half * 24);
#pragma unroll
        for (int j = 0; j < 12; j++) {
            float2 v = unpack2(acc[j]);
            out[half * 24 + 2 * j]     = v.x;
            out[half * 24 + 2 * j + 1] = v.y;
        }
    }
}

// ---------- kernels ----------

__global__ void embed_kernel(const int* __restrict__ an, const float4* __restrict__ emb4) {
    int i = blockIdx.x * blockDim.x + threadIdx.x;
    if (i >= NN * 12) return;
    int node = i / 12;
    int v = i - node * 12;
    g_h[i] = emb4[an[node] * 12 + v];
    g_agg[i] = make_float4(0.f, 0.f, 0.f, 0.f);
}

__device__ __forceinline__ void load_weights_smem(float* s,
                                                  const float* __restrict__ w1, const float* __restrict__ b1,
                                                  const float* __restrict__ w2, const float* __restrict__ b2,
                                                  int layer) {
    const float* lw1 = w1 + layer * D * D;
    const float* lw2 = w2 + layer * D * D;
    for (int i = threadIdx.x; i < D * D; i += blockDim.x) {
        s[i] = lw1[i];
        s[2304 + i] = lw2[i];
    }
    if (threadIdx.x < D) {
        s[4608 + threadIdx.x] = b1[layer * D + threadIdx.x];
        s[4656 + threadIdx.x] = b2[layer * D + threadIdx.x];
    }
    __syncthreads();
}

__global__ __launch_bounds__(256, 2) void update_kernel(
    const float* __restrict__ w1, const float* __restrict__ b1,
    const float* __restrict__ w2, const float* __restrict__ b2, int layer) {
    __shared__ __align__(16) float s[4704];
    load_weights_smem(s, w1, b1, w2, b2, layer);

    int n = blockIdx.x * 256 + threadIdx.x;
    if (n >= NN) return;

    float4* aggp = &g_agg[n * 12];
    float x[D];
    const float4 z = make_float4(0.f, 0.f, 0.f, 0.f);
#pragma unroll
    for (int v = 0; v < 12; v++) {
        float4 a = aggp[v];
        x[4 * v + 0] = a.x;
        x[4 * v + 1] = a.y;
        x[4 * v + 2] = a.z;
        x[4 * v + 3] = a.w;
        aggp[v] = z;
    }

    float u[D];
    mlp2_48(x, u, s, s + 4608, s + 2304, s + 4656);

    float4* hp = &g_h[n * 12];
#pragma unroll
    for (int v = 0; v < 12; v++) {
        float4 h = hp[v];
        h.x += u[4 * v + 0];
        h.y += u[4 * v + 1];
        h.z += u[4 * v + 2];
        h.w += u[4 * v + 3];
        hp[v] = h;
    }
}

__global__ __launch_bounds__(256, 2) void readout_kernel(
    const int* __restrict__ gid,
    const float* __restrict__ rw1, const float* __restrict__ rb1,
    const float* __restrict__ rw2, const float* __restrict__ rb2,
    float* __restrict__ out) {
    __shared__ __align__(16) float s[2402];
    for (int i = threadIdx.x; i < D * D; i += blockDim.x) s[i] = rw1[i];
    if (threadIdx.x < D) {
        s[2304 + threadIdx.x] = rb1[threadIdx.x];
        s[2352 + threadIdx.x] = rw2[threadIdx.x];
    }
    if (threadIdx.x == 0) s[2400] = rb2[0];
    __syncthreads();

    int n = blockIdx.x * 256 + threadIdx.x;
    if (n >= NN) return;

    const float4* hp = &g_h[n * 12];
    float x[D];
#pragma unroll
    for (int v = 0; v < 12; v++) {
        float4 a = hp[v];
        x[4 * v + 0] = a.x;
        x[4 * v + 1] = a.y;
        x[4 * v + 2] = a.z;
        x[4 * v + 3] = a.w;
    }

    float y = s[2400];
#pragma unroll 1
    for (int half = 0; half < 2; half++) {
        u64 acc[12];
        gemm48_half(x, acc, s + half * 24, s + 2304 + half * 24);
#pragma unroll
        for (int j = 0; j < 12; j++) {
            float2 v = unpack2(acc[j]);
            y += fmaxf(v.x, 0.f) * s[2352 + half * 24 + 2 * j];
            y += fmaxf(v.y, 0.f) * s[2352 + half * 24 + 2 * j + 1];
        }
    }

    atomicAdd(&out[gid[n]], y);
}

extern "C" void kernel_launch(void* const* d_in, const int* in_sizes, int n_in,
                              void* d_out, int out_size) {
    const int*   an   = (const int*)d_in[0];
    const int*   edge = (const int*)d_in[1];
    const int*   gid  = (const int*)d_in[2];
    const float* emb  = (const float*)d_in[3];
    const float* mw1  = (const float*)d_in[4];
    const float* mb1  = (const float*)d_in[5];
    const float* mw2  = (const float*)d_in[6];
    const float* mb2  = (const float*)d_in[7];
    const float* uw1  = (const float*)d_in[8];
    const float* ub1  = (const float*)d_in[9];
    const float* uw2  = (const float*)d_in[10];
    const float* ub2  = (const float*)d_in[11];
    const float* rw1  = (const float*)d_in[12];
    const float* rb1  = (const float*)d_in[13];
    const float* rw2  = (const float*)d_in[14];
    const float* rb2  = (const float*)d_in[15];
    float* out = (float*)d_out;

    const int edge_smem = EDGE_SMEM_FLOATS * (int)sizeof(float);  // ~108 KB
    cudaFuncSetAttribute(edge_wmma_kernel, cudaFuncAttributeMaxDynamicSharedMemorySize, edge_smem);

    // counting sort of edges by dst (edge list constant across layers)
    zero_cnt_kernel<<<(NN + 255) / 256, 256>>>();
    hist_kernel<<<(NE + 255) / 256, 256>>>(edge);
    scan1_kernel<<<NSCAN_BLKS, SCAN_BLK>>>();
    scan2_kernel<<<1, 32>>>();
    scan3_kernel<<<(NN + 255) / 256, 256>>>();
    scatter_sort_kernel<<<(NE + 255) / 256, 256>>>(edge);

    embed_kernel<<<(NN * 12 + 255) / 256, 256>>>(an, (const float4*)emb);

    for (int l = 0; l < NCONVS; l++) {
        edge_wmma_kernel<<<NE / EPC, 128, edge_smem>>>(mw1, mb1, mw2, mb2, l);
        update_kernel<<<(NN + 255) / 256, 256>>>(uw1, ub1, uw2, ub2, l);
    }

    cudaMemsetAsync(out, 0, NG * sizeof(float));
    readout_kernel<<<(NN + 255) / 256, 256>>>(gid, rw1, rb1, rw2, rb2, out);
}

// round 10
// speedup vs baseline: 1.8537x; 1.8537x over previous
#include <cuda_runtime.h>

#define NN 100000
#define NE 1600000
#define D 48
#define NCONVS 6
#define NG 1000

#define EPC 256     // edges per CTA (128 threads, 2 consecutive edges/thread)
#define XSTRIDE 52  // x row stride in floats: 208B = 13*16B -> float4-aligned rows,
                    // conflict-free LDS.128 (52*t mod 32 banks distinct per 8-lane phase)

#define SCAN_BLK 1024
#define NSCAN_BLKS ((NN + SCAN_BLK - 1) / SCAN_BLK)   // 98

typedef unsigned long long u64;

// Scratch state (no allocation allowed).
__device__ float4 g_h[NN * 12];
__device__ float4 g_agg[NN * 12];
// counting-sort scratch
__device__ int g_cnt[NN];
__device__ int g_scan[NN];
__device__ int g_bsum[NSCAN_BLKS];
__device__ int g_woff[NN];
__device__ int g_ssrc[NE];
__device__ int g_sdst[NE];

// ---------- packed f32x2 helpers ----------
__device__ __forceinline__ u64 fma2(u64 a, u64 b, u64 c) {
    u64 d;
    asm("fma.rn.f32x2 %0, %1, %2, %3;" : "=l"(d) : "l"(a), "l"(b), "l"(c));
    return d;
}
__device__ __forceinline__ u64 add2(u64 a, u64 b) {
    u64 d;
    asm("add.rn.f32x2 %0, %1, %2;" : "=l"(d) : "l"(a), "l"(b));
    return d;
}
__device__ __forceinline__ u64 pack2(float lo, float hi) {
    u64 r;
    asm("mov.b64 %0, {%1, %2};" : "=l"(r) : "f"(lo), "f"(hi));
    return r;
}
__device__ __forceinline__ float2 unpack2(u64 v) {
    float2 f;
    asm("mov.b64 {%0, %1}, %2;" : "=f"(f.x), "=f"(f.y) : "l"(v));
    return f;
}

// ---------- counting sort by dst ----------
__global__ void zero_cnt_kernel() {
    int i = blockIdx.x * blockDim.x + threadIdx.x;
    if (i < NN) g_cnt[i] = 0;
}
__global__ void hist_kernel(const int* __restrict__ edge) {
    int e = blockIdx.x * blockDim.x + threadIdx.x;
    if (e < NE) atomicAdd(&g_cnt[edge[NE + e]], 1);
}
__global__ void scan1_kernel() {
    __shared__ int sh[SCAN_BLK];
    int tid = threadIdx.x;
    int i = blockIdx.x * SCAN_BLK + tid;
    int v = (i < NN) ? g_cnt[i] : 0;
    sh[tid] = v;
    __syncthreads();
#pragma unroll
    for (int o = 1; o < SCAN_BLK; o <<= 1) {
        int t = (tid >= o) ? sh[tid - o] : 0;
        __syncthreads();
        sh[tid] += t;
        __syncthreads();
    }
    if (i < NN) g_scan[i] = sh[tid];
    if (tid == SCAN_BLK - 1) g_bsum[blockIdx.x] = sh[tid];
}
__global__ void scan2_kernel() {
    if (threadIdx.x == 0 && blockIdx.x == 0) {
        int acc = 0;
        for (int b = 0; b < NSCAN_BLKS; b++) {
            int t = g_bsum[b];
            g_bsum[b] = acc;
            acc += t;
        }
    }
}
__global__ void scan3_kernel() {
    int i = blockIdx.x * blockDim.x + threadIdx.x;
    if (i < NN) g_woff[i] = g_scan[i] - g_cnt[i] + g_bsum[i / SCAN_BLK];
}
__global__ void scatter_sort_kernel(const int* __restrict__ edge) {
    int e = blockIdx.x * blockDim.x + threadIdx.x;
    if (e >= NE) return;
    int d = edge[NE + e];
    int pos = atomicAdd(&g_woff[d], 1);
    g_ssrc[pos] = edge[e];
    g_sdst[pos] = d;
}

// ---------- dual-row full-width GEMM, x from SMEM via float4 ----------
__device__ __forceinline__ void gemm48_dual_smem(const float* __restrict__ x0,
                                                 const float* __restrict__ x1,
                                                 u64 acc0[24], u64 acc1[24],
                                                 const float* __restrict__ ws,
                                                 const float* __restrict__ bs) {
#pragma unroll
    for (int j = 0; j < 24; j++) {
        u64 b = *(const u64*)(bs + 2 * j);
        acc0[j] = b;
        acc1[j] = b;
    }
#pragma unroll 3
    for (int kk = 0; kk < 12; kk++) {
        float4 xa = *(const float4*)(x0 + 4 * kk);
        float4 xb = *(const float4*)(x1 + 4 * kk);
        float a0q[4] = {xa.x, xa.y, xa.z, xa.w};
        float a1q[4] = {xb.x, xb.y, xb.z, xb.w};
#pragma unroll
        for (int kq = 0; kq < 4; kq++) {
            int k = 4 * kk + kq;
            u64 xk0 = pack2(a0q[kq], a0q[kq]);
            u64 xk1 = pack2(a1q[kq], a1q[kq]);
            const ulonglong2* wr = (const ulonglong2*)(ws + k * D);
#pragma unroll
            for (int jj = 0; jj < 12; jj++) {
                ulonglong2 w = wr[jj];
                acc0[2 * jj]     = fma2(xk0, w.x, acc0[2 * jj]);
                acc0[2 * jj + 1] = fma2(xk0, w.y, acc0[2 * jj + 1]);
                acc1[2 * jj]     = fma2(xk1, w.x, acc1[2 * jj]);
                acc1[2 * jj + 1] = fma2(xk1, w.y, acc1[2 * jj + 1]);
            }
        }
    }
}

// relu accumulators back into own smem x rows (STS.64), no sync needed
__device__ __forceinline__ void relu_writeback(float* x, const u64 a[24]) {
#pragma unroll
    for (int j = 0; j < 24; j++) {
        float2 v = unpack2(a[j]);
        *(u64*)(x + 2 * j) = pack2(fmaxf(v.x, 0.f), fmaxf(v.y, 0.f));
    }
}

// ---------- single-row half GEMM (readout) ----------
__device__ __forceinline__ void gemm48_half(const float x[D], u64 acc[12],
                                            const float* __restrict__ ws,
                                            const float* __restrict__ bs) {
#pragma unroll
    for (int j = 0; j < 12; j++) acc[j] = *(const u64*)(bs + 2 * j);
#pragma unroll 4
    for (int k = 0; k < D; k++) {
        u64 xk = pack2(x[k], x[k]);
        const ulonglong2* wr = (const ulonglong2*)(ws + k * D);
#pragma unroll
        for (int jj = 0; jj < 6; jj++) {
            ulonglong2 w = wr[jj];
            acc[2 * jj]     = fma2(xk, w.x, acc[2 * jj]);
            acc[2 * jj + 1] = fma2(xk, w.y, acc[2 * jj + 1]);
        }
    }
}

// ---------- kernels ----------

__global__ void embed_kernel(const int* __restrict__ an, const float4* __restrict__ emb4) {
    int i = blockIdx.x * blockDim.x + threadIdx.x;
    if (i >= NN * 12) return;
    int node = i / 12;
    int v = i - node * 12;
    g_h[i] = emb4[an[node] * 12 + v];
    g_agg[i] = make_float4(0.f, 0.f, 0.f, 0.f);
}

__device__ __forceinline__ void scatter48(float* aggp, const u64 a[24]) {
#pragma unroll
    for (int v = 0; v < 6; v++) {
        float2 p0 = unpack2(a[4 * v + 0]);
        float2 p1 = unpack2(a[4 * v + 1]);
        float2 p2 = unpack2(a[4 * v + 2]);
        float2 p3 = unpack2(a[4 * v + 3]);
        asm volatile("red.global.add.v4.f32 [%0], {%1, %2, %3, %4};"
                     :: "l"(aggp + 8 * v), "f"(p0.x), "f"(p0.y), "f"(p1.x), "f"(p1.y) : "memory");
        asm volatile("red.global.add.v4.f32 [%0], {%1, %2, %3, %4};"
                     :: "l"(aggp + 8 * v + 4), "f"(p2.x), "f"(p2.y), "f"(p3.x), "f"(p3.y) : "memory");
    }
}

// SMEM: [0:2304) w1, [2304:4608) w2, [4608:4656) b1, [4656:4704) b2,
//       [4704: +256*52) x rows. Edge el -> row ((el&1)<<7)+(el>>1): phase-2
//       thread t owns rows t,t+128 = edges 2t,2t+1 (consecutive after dst-sort).
#define EDGE_SMEM_FLOATS (4704 + EPC * XSTRIDE)

__global__ __launch_bounds__(128, 3) void edge_kernel(
    const float* __restrict__ w1, const float* __restrict__ b1,
    const float* __restrict__ w2, const float* __restrict__ b2, int layer) {
    extern __shared__ __align__(16) float s[];
    float* xs = s + 4704;
    int tid = threadIdx.x;

    const float* lw1 = w1 + layer * D * D;
    const float* lw2 = w2 + layer * D * D;
#pragma unroll
    for (int i = tid; i < D * D; i += 128) {
        s[i] = lw1[i];
        s[2304 + i] = lw2[i];
    }
    if (tid < D) {
        s[4608 + tid] = b1[layer * D + tid];
        s[4656 + tid] = b2[layer * D + tid];
    }

    // Phase 1: coalesced gather, 4 lanes per edge, float4 smem stores.
    int e_base = blockIdx.x * EPC;
#pragma unroll
    for (int it = 0; it < 8; it++) {
        int idx = it * 128 + tid;      // 0..1023
        int el = idx >> 2;             // local edge 0..255
        int ch = idx & 3;              // chunk 0..3
        int e = e_base + el;
        int sn = g_ssrc[e];
        int dn = g_sdst[e];
        const float4* hs = (const float4*)&g_h[sn * 12] + ch * 3;
        const float4* hd = (const float4*)&g_h[dn * 12] + ch * 3;
        int row = ((el & 1) << 7) + (el >> 1);
        float4* xrow = (float4*)(xs + row * XSTRIDE + ch * 12);
#pragma unroll
        for (int i = 0; i < 3; i++) {
            float4 a = hs[i];
            float4 b = hd[i];
            xrow[i] = make_float4(a.x * b.x, a.y * b.y, a.z * b.z, a.w * b.w);
        }
    }
    __syncthreads();

    // Phase 2: dual consecutive edges 2t, 2t+1.
    float* x0 = xs + tid * XSTRIDE;
    float* x1 = xs + (tid + 128) * XSTRIDE;

    {
        u64 a0[24], a1[24];
        gemm48_dual_smem(x0, x1, a0, a1, s, s + 4608);
        relu_writeback(x0, a0);
        relu_writeback(x1, a1);
    }

    u64 a0[24], a1[24];
    gemm48_dual_smem(x0, x1, a0, a1, s + 2304, s + 4656);

    int e0 = e_base + 2 * tid;
    int dst0 = g_sdst[e0];
    int dst1 = g_sdst[e0 + 1];
    if (dst0 == dst1) {
#pragma unroll
        for (int j = 0; j < 24; j++) a0[j] = add2(a0[j], a1[j]);
        scatter48((float*)&g_agg[dst0 * 12], a0);
    } else {
        scatter48((float*)&g_agg[dst0 * 12], a0);
        scatter48((float*)&g_agg[dst1 * 12], a1);
    }
}

// Dual-node update kernel: same structure as edge kernel (weights amortized
// over 2 nodes, x staged in smem), plus agg zeroing and residual h update.
__global__ __launch_bounds__(128, 3) void update_kernel(
    const float* __restrict__ w1, const float* __restrict__ b1,
    const float* __restrict__ w2, const float* __restrict__ b2, int layer) {
    extern __shared__ __align__(16) float s[];
    float* xs = s + 4704;
    int tid = threadIdx.x;

    const float* lw1 = w1 + layer * D * D;
    const float* lw2 = w2 + layer * D * D;
#pragma unroll
    for (int i = tid; i < D * D; i += 128) {
        s[i] = lw1[i];
        s[2304 + i] = lw2[i];
    }
    if (tid < D) {
        s[4608 + tid] = b1[layer * D + tid];
        s[4656 + tid] = b2[layer * D + tid];
    }

    int n_base = blockIdx.x * 256;
    const float4 z = make_float4(0.f, 0.f, 0.f, 0.f);
#pragma unroll
    for (int it = 0; it < 8; it++) {
        int idx = it * 128 + tid;
        int nl = idx >> 2;
        int ch = idx & 3;
        int n = n_base + nl;
        if (n < NN) {
            float4* ap = &g_agg[n * 12] + ch * 3;
            int row = ((nl & 1) << 7) + (nl >> 1);
            float4* xrow = (float4*)(xs + row * XSTRIDE + ch * 12);
#pragma unroll
            for (int i = 0; i < 3; i++) {
                xrow[i] = ap[i];
                ap[i] = z;  // reset for next layer's scatter
            }
        }
    }
    __syncthreads();

    int n0 = n_base + 2 * tid;
    if (n0 >= NN) return;
    int n1 = n0 + 1;

    float* x0 = xs + tid * XSTRIDE;
    float* x1 = xs + (tid + 128) * XSTRIDE;

    {
        u64 a0[24], a1[24];
        gemm48_dual_smem(x0, x1, a0, a1, s, s + 4608);
        relu_writeback(x0, a0);
        relu_writeback(x1, a1);
    }

    u64 a0[24], a1[24];
    gemm48_dual_smem(x0, x1, a0, a1, s + 2304, s + 4656);

    {
        float4* hp = &g_h[n0 * 12];
#pragma unroll
        for (int v = 0; v < 12; v++) {
            float2 p0 = unpack2(a0[2 * v]);
            float2 p1 = unpack2(a0[2 * v + 1]);
            float4 h = hp[v];
            h.x += p0.x; h.y += p0.y; h.z += p1.x; h.w += p1.y;
            hp[v] = h;
        }
    }
    if (n1 < NN) {
        float4* hp = &g_h[n1 * 12];
#pragma unroll
        for (int v = 0; v < 12; v++) {
            float2 p0 = unpack2(a1[2 * v]);
            float2 p1 = unpack2(a1[2 * v + 1]);
            float4 h = hp[v];
            h.x += p0.x; h.y += p0.y; h.z += p1.x; h.w += p1.y;
            hp[v] = h;
        }
    }
}

__global__ __launch_bounds__(256, 2) void readout_kernel(
    const int* __restrict__ gid,
    const float* __restrict__ rw1, const float* __restrict__ rb1,
    const float* __restrict__ rw2, const float* __restrict__ rb2,
    float* __restrict__ out) {
    __shared__ __align__(16) float s[2402];
    for (int i = threadIdx.x; i < D * D; i += blockDim.x) s[i] = rw1[i];
    if (threadIdx.x < D) {
        s[2304 + threadIdx.x] = rb1[threadIdx.x];
        s[2352 + threadIdx.x] = rw2[threadIdx.x];
    }
    if (threadIdx.x == 0) s[2400] = rb2[0];
    __syncthreads();

    int n = blockIdx.x * 256 + threadIdx.x;
    if (n >= NN) return;

    const float4* hp = &g_h[n * 12];
    float x[D];
#pragma unroll
    for (int v = 0; v < 12; v++) {
        float4 a = hp[v];
        x[4 * v + 0] = a.x;
        x[4 * v + 1] = a.y;
        x[4 * v + 2] = a.z;
        x[4 * v + 3] = a.w;
    }

    float y = s[2400];
#pragma unroll 1
    for (int half = 0; half < 2; half++) {
        u64 acc[12];
        gemm48_half(x, acc, s + half * 24, s + 2304 + half * 24);
#pragma unroll
        for (int j = 0; j < 12; j++) {
            float2 v = unpack2(acc[j]);
            y += fmaxf(v.x, 0.f) * s[2352 + half * 24 + 2 * j];
            y += fmaxf(v.y, 0.f) * s[2352 + half * 24 + 2 * j + 1];
        }
    }

    atomicAdd(&out[gid[n]], y);
}

extern "C" void kernel_launch(void* const* d_in, const int* in_sizes, int n_in,
                              void* d_out, int out_size) {
    const int*   an   = (const int*)d_in[0];
    const int*   edge = (const int*)d_in[1];
    const int*   gid  = (const int*)d_in[2];
    const float* emb  = (const float*)d_in[3];
    const float* mw1  = (const float*)d_in[4];
    const float* mb1  = (const float*)d_in[5];
    const float* mw2  = (const float*)d_in[6];
    const float* mb2  = (const float*)d_in[7];
    const float* uw1  = (const float*)d_in[8];
    const float* ub1  = (const float*)d_in[9];
    const float* uw2  = (const float*)d_in[10];
    const float* ub2  = (const float*)d_in[11];
    const float* rw1  = (const float*)d_in[12];
    const float* rb1  = (const float*)d_in[13];
    const float* rw2  = (const float*)d_in[14];
    const float* rb2  = (const float*)d_in[15];
    float* out = (float*)d_out;

    const int edge_smem = EDGE_SMEM_FLOATS * (int)sizeof(float);  // ~72 KB
    cudaFuncSetAttribute(edge_kernel, cudaFuncAttributeMaxDynamicSharedMemorySize, edge_smem);
    cudaFuncSetAttribute(update_kernel, cudaFuncAttributeMaxDynamicSharedMemorySize, edge_smem);

    // counting sort of edges by dst (edge list constant across layers)
    zero_cnt_kernel<<<(NN + 255) / 256, 256>>>();
    hist_kernel<<<(NE + 255) / 256, 256>>>(edge);
    scan1_kernel<<<NSCAN_BLKS, SCAN_BLK>>>();
    scan2_kernel<<<1, 32>>>();
    scan3_kernel<<<(NN + 255) / 256, 256>>>();
    scatter_sort_kernel<<<(NE + 255) / 256, 256>>>(edge);

    embed_kernel<<<(NN * 12 + 255) / 256, 256>>>(an, (const float4*)emb);

    for (int l = 0; l < NCONVS; l++) {
        edge_kernel<<<NE / EPC, 128, edge_smem>>>(mw1, mb1, mw2, mb2, l);
        update_kernel<<<(NN + 255) / 256, 128, edge_smem>>>(uw1, ub1, uw2, ub2, l);
    }

    cudaMemsetAsync(out, 0, NG * sizeof(float));
    readout_kernel<<<(NN + 255) / 256, 256>>>(gid, rw1, rb1, rw2, rb2, out);
}

// round 11
// speedup vs baseline: 1.9222x; 1.0369x over previous
#include <cuda_runtime.h>

#define NN 100000
#define NE 1600000
#define D 48
#define NCONVS 6
#define NG 1000

#define EPC 256     // edges per CTA (128 threads, 2 consecutive edges/thread)
#define XSTRIDE 49  // padded x row stride in floats (odd -> conflict-free scalar LDS)

#define SCAN_BLK 1024
#define NSCAN_BLKS ((NN + SCAN_BLK - 1) / SCAN_BLK)   // 98

typedef unsigned long long u64;

// Scratch state (no allocation allowed).
__device__ float4 g_h[NN * 12];
__device__ float4 g_agg[NN * 12];
// counting-sort scratch
__device__ int g_cnt[NN];
__device__ int g_scan[NN];
__device__ int g_bsum[NSCAN_BLKS];
__device__ int g_woff[NN];
__device__ int g_ssrc[NE];
__device__ int g_sdst[NE];

// ---------- packed f32x2 helpers ----------
__device__ __forceinline__ u64 fma2(u64 a, u64 b, u64 c) {
    u64 d;
    asm("fma.rn.f32x2 %0, %1, %2, %3;" : "=l"(d) : "l"(a), "l"(b), "l"(c));
    return d;
}
__device__ __forceinline__ u64 add2(u64 a, u64 b) {
    u64 d;
    asm("add.rn.f32x2 %0, %1, %2;" : "=l"(d) : "l"(a), "l"(b));
    return d;
}
__device__ __forceinline__ u64 pack2(float lo, float hi) {
    u64 r;
    asm("mov.b64 %0, {%1, %2};" : "=l"(r) : "f"(lo), "f"(hi));
    return r;
}
__device__ __forceinline__ float2 unpack2(u64 v) {
    float2 f;
    asm("mov.b64 {%0, %1}, %2;" : "=f"(f.x), "=f"(f.y) : "l"(v));
    return f;
}

// ---------- counting sort by dst ----------
__global__ void zero_cnt_kernel() {
    int i = blockIdx.x * blockDim.x + threadIdx.x;
    if (i < NN) g_cnt[i] = 0;
}
__global__ void hist_kernel(const int* __restrict__ edge) {
    int e = blockIdx.x * blockDim.x + threadIdx.x;
    if (e < NE) atomicAdd(&g_cnt[edge[NE + e]], 1);
}
__global__ void scan1_kernel() {
    __shared__ int sh[SCAN_BLK];
    int tid = threadIdx.x;
    int i = blockIdx.x * SCAN_BLK + tid;
    int v = (i < NN) ? g_cnt[i] : 0;
    sh[tid] = v;
    __syncthreads();
#pragma unroll
    for (int o = 1; o < SCAN_BLK; o <<= 1) {
        int t = (tid >= o) ? sh[tid - o] : 0;
        __syncthreads();
        sh[tid] += t;
        __syncthreads();
    }
    if (i < NN) g_scan[i] = sh[tid];
    if (tid == SCAN_BLK - 1) g_bsum[blockIdx.x] = sh[tid];
}
__global__ void scan2_kernel() {
    if (threadIdx.x == 0 && blockIdx.x == 0) {
        int acc = 0;
        for (int b = 0; b < NSCAN_BLKS; b++) {
            int t = g_bsum[b];
            g_bsum[b] = acc;
            acc += t;
        }
    }
}
__global__ void scan3_kernel() {
    int i = blockIdx.x * blockDim.x + threadIdx.x;
    if (i < NN) g_woff[i] = g_scan[i] - g_cnt[i] + g_bsum[i / SCAN_BLK];
}
__global__ void scatter_sort_kernel(const int* __restrict__ edge) {
    int e = blockIdx.x * blockDim.x + threadIdx.x;
    if (e >= NE) return;
    int d = edge[NE + e];
    int pos = atomicAdd(&g_woff[d], 1);
    g_ssrc[pos] = edge[e];
    g_sdst[pos] = d;
}

// ---------- dual-row full-width GEMM reading x from SMEM (scalar LDS) ----------
__device__ __forceinline__ void gemm48_dual_smem(const float* __restrict__ x0,
                                                 const float* __restrict__ x1,
                                                 u64 acc0[24], u64 acc1[24],
                                                 const float* __restrict__ ws,
                                                 const float* __restrict__ bs) {
#pragma unroll
    for (int j = 0; j < 24; j++) {
        u64 b = *(const u64*)(bs + 2 * j);
        acc0[j] = b;
        acc1[j] = b;
    }
#pragma unroll 4
    for (int k = 0; k < D; k++) {
        float a0 = x0[k];
        float a1 = x1[k];
        u64 xk0 = pack2(a0, a0);
        u64 xk1 = pack2(a1, a1);
        const ulonglong2* wr = (const ulonglong2*)(ws + k * D);
#pragma unroll
        for (int jj = 0; jj < 12; jj++) {
            ulonglong2 w = wr[jj];
            acc0[2 * jj]     = fma2(xk0, w.x, acc0[2 * jj]);
            acc0[2 * jj + 1] = fma2(xk0, w.y, acc0[2 * jj + 1]);
            acc1[2 * jj]     = fma2(xk1, w.x, acc1[2 * jj]);
            acc1[2 * jj + 1] = fma2(xk1, w.y, acc1[2 * jj + 1]);
        }
    }
}

// relu accumulators back into own smem x rows (same-thread, no sync needed)
__device__ __forceinline__ void relu_writeback(float* x, const u64 a[24]) {
#pragma unroll
    for (int j = 0; j < 24; j++) {
        float2 v = unpack2(a[j]);
        x[2 * j]     = fmaxf(v.x, 0.f);
        x[2 * j + 1] = fmaxf(v.y, 0.f);
    }
}

// ---------- single-row half GEMM (readout) ----------
__device__ __forceinline__ void gemm48_half(const float x[D], u64 acc[12],
                                            const float* __restrict__ ws,
                                            const float* __restrict__ bs) {
#pragma unroll
    for (int j = 0; j < 12; j++) acc[j] = *(const u64*)(bs + 2 * j);
#pragma unroll 4
    for (int k = 0; k < D; k++) {
        u64 xk = pack2(x[k], x[k]);
        const ulonglong2* wr = (const ulonglong2*)(ws + k * D);
#pragma unroll
        for (int jj = 0; jj < 6; jj++) {
            ulonglong2 w = wr[jj];
            acc[2 * jj]     = fma2(xk, w.x, acc[2 * jj]);
            acc[2 * jj + 1] = fma2(xk, w.y, acc[2 * jj + 1]);
        }
    }
}

// ---------- kernels ----------

__global__ void embed_kernel(const int* __restrict__ an, const float4* __restrict__ emb4) {
    int i = blockIdx.x * blockDim.x + threadIdx.x;
    if (i >= NN * 12) return;
    int node = i / 12;
    int v = i - node * 12;
    g_h[i] = emb4[an[node] * 12 + v];
    g_agg[i] = make_float4(0.f, 0.f, 0.f, 0.f);
}

__device__ __forceinline__ void scatter48(float* aggp, const u64 a[24]) {
#pragma unroll
    for (int v = 0; v < 6; v++) {
        float2 p0 = unpack2(a[4 * v + 0]);
        float2 p1 = unpack2(a[4 * v + 1]);
        float2 p2 = unpack2(a[4 * v + 2]);
        float2 p3 = unpack2(a[4 * v + 3]);
        asm volatile("red.global.add.v4.f32 [%0], {%1, %2, %3, %4};"
                     :: "l"(aggp + 8 * v), "f"(p0.x), "f"(p0.y), "f"(p1.x), "f"(p1.y) : "memory");
        asm volatile("red.global.add.v4.f32 [%0], {%1, %2, %3, %4};"
                     :: "l"(aggp + 8 * v + 4), "f"(p2.x), "f"(p2.y), "f"(p3.x), "f"(p3.y) : "memory");
    }
}

// SMEM (floats): [0:2304) w1, [2304:4608) w2, [4608:4656) b1, [4656:4704) b2,
// [4704:4960) esrc (256 int), [4960:5216) edst (256 int),
// [5216: +256*49) x rows. Edge el -> row ((el&1)<<7)+(el>>1): phase-2 thread t
// owns rows t, t+128 = edges 2t, 2t+1 (consecutive after dst-sort).
#define OFF_ESRC 4704
#define OFF_EDST 4960
#define OFF_X    5216
#define EDGE_SMEM_FLOATS (OFF_X + EPC * XSTRIDE)

__global__ __launch_bounds__(128, 3) void edge_kernel(
    const float* __restrict__ w1, const float* __restrict__ b1,
    const float* __restrict__ w2, const float* __restrict__ b2, int layer) {
    extern __shared__ __align__(16) float s[];
    float* xs = s + OFF_X;
    int* esrc = (int*)(s + OFF_ESRC);
    int* edst = (int*)(s + OFF_EDST);
    int tid = threadIdx.x;

    const float* lw1 = w1 + layer * D * D;
    const float* lw2 = w2 + layer * D * D;
#pragma unroll
    for (int i = tid; i < D * D; i += 128) {
        s[i] = lw1[i];
        s[2304 + i] = lw2[i];
    }
    if (tid < D) {
        s[4608 + tid] = b1[layer * D + tid];
        s[4656 + tid] = b2[layer * D + tid];
    }

    // Stage edge ids coalescedly (2 int4-equivalent loads per thread).
    int e_base = blockIdx.x * EPC;
#pragma unroll
    for (int i = tid; i < EPC; i += 128) {
        esrc[i] = g_ssrc[e_base + i];
        edst[i] = g_sdst[e_base + i];
    }
    __syncthreads();

    // Phase 1: coalesced gather, 4 lanes per edge (ids via broadcast LDS).
#pragma unroll
    for (int it = 0; it < 8; it++) {
        int idx = it * 128 + tid;      // 0..1023
        int el = idx >> 2;             // local edge 0..255
        int ch = idx & 3;              // chunk 0..3
        int sn = esrc[el];
        int dn = edst[el];
        const float4* hs = (const float4*)&g_h[sn * 12] + ch * 3;
        const float4* hd = (const float4*)&g_h[dn * 12] + ch * 3;
        int row = ((el & 1) << 7) + (el >> 1);
        float* xrow = xs + row * XSTRIDE + ch * 12;
#pragma unroll
        for (int i = 0; i < 3; i++) {
            float4 a = hs[i];
            float4 b = hd[i];
            xrow[4 * i + 0] = a.x * b.x;
            xrow[4 * i + 1] = a.y * b.y;
            xrow[4 * i + 2] = a.z * b.z;
            xrow[4 * i + 3] = a.w * b.w;
        }
    }
    __syncthreads();

    // Phase 2: dual consecutive edges 2t, 2t+1.
    float* x0 = xs + tid * XSTRIDE;
    float* x1 = xs + (tid + 128) * XSTRIDE;

    {
        u64 a0[24], a1[24];
        gemm48_dual_smem(x0, x1, a0, a1, s, s + 4608);
        relu_writeback(x0, a0);
        relu_writeback(x1, a1);
    }

    u64 a0[24], a1[24];
    gemm48_dual_smem(x0, x1, a0, a1, s + 2304, s + 4656);

    int dst0 = edst[2 * tid];
    int dst1 = edst[2 * tid + 1];
    if (dst0 == dst1) {
#pragma unroll
        for (int j = 0; j < 24; j++) a0[j] = add2(a0[j], a1[j]);
        scatter48((float*)&g_agg[dst0 * 12], a0);
    } else {
        scatter48((float*)&g_agg[dst0 * 12], a0);
        scatter48((float*)&g_agg[dst1 * 12], a1);
    }
}

// Dual-node update kernel: R8 edge structure applied to nodes (weights
// amortized over 2 nodes, x staged in smem scalar), agg zeroing + residual.
__global__ __launch_bounds__(128, 3) void update_kernel(
    const float* __restrict__ w1, const float* __restrict__ b1,
    const float* __restrict__ w2, const float* __restrict__ b2, int layer) {
    extern __shared__ __align__(16) float s[];
    float* xs = s + OFF_X;
    int tid = threadIdx.x;

    const float* lw1 = w1 + layer * D * D;
    const float* lw2 = w2 + layer * D * D;
#pragma unroll
    for (int i = tid; i < D * D; i += 128) {
        s[i] = lw1[i];
        s[2304 + i] = lw2[i];
    }
    if (tid < D) {
        s[4608 + tid] = b1[layer * D + tid];
        s[4656 + tid] = b2[layer * D + tid];
    }

    int n_base = blockIdx.x * 256;
    const float4 z = make_float4(0.f, 0.f, 0.f, 0.f);
#pragma unroll
    for (int it = 0; it < 8; it++) {
        int idx = it * 128 + tid;
        int nl = idx >> 2;
        int ch = idx & 3;
        int n = n_base + nl;
        if (n < NN) {
            float4* ap = &g_agg[n * 12] + ch * 3;
            int row = ((nl & 1) << 7) + (nl >> 1);
            float* xrow = xs + row * XSTRIDE + ch * 12;
#pragma unroll
            for (int i = 0; i < 3; i++) {
                float4 a = ap[i];
                xrow[4 * i + 0] = a.x;
                xrow[4 * i + 1] = a.y;
                xrow[4 * i + 2] = a.z;
                xrow[4 * i + 3] = a.w;
                ap[i] = z;  // reset for next layer's scatter
            }
        }
    }
    __syncthreads();

    int n0 = n_base + 2 * tid;
    if (n0 >= NN) return;
    int n1 = n0 + 1;

    float* x0 = xs + tid * XSTRIDE;
    float* x1 = xs + (tid + 128) * XSTRIDE;

    {
        u64 a0[24], a1[24];
        gemm48_dual_smem(x0, x1, a0, a1, s, s + 4608);
        relu_writeback(x0, a0);
        relu_writeback(x1, a1);
    }

    u64 a0[24], a1[24];
    gemm48_dual_smem(x0, x1, a0, a1, s + 2304, s + 4656);

    {
        float4* hp = &g_h[n0 * 12];
#pragma unroll
        for (int v = 0; v < 12; v++) {
            float2 p0 = unpack2(a0[2 * v]);
            float2 p1 = unpack2(a0[2 * v + 1]);
            float4 h = hp[v];
            h.x += p0.x; h.y += p0.y; h.z += p1.x; h.w += p1.y;
            hp[v] = h;
        }
    }
    if (n1 < NN) {
        float4* hp = &g_h[n1 * 12];
#pragma unroll
        for (int v = 0; v < 12; v++) {
            float2 p0 = unpack2(a1[2 * v]);
            float2 p1 = unpack2(a1[2 * v + 1]);
            float4 h = hp[v];
            h.x += p0.x; h.y += p0.y; h.z += p1.x; h.w += p1.y;
            hp[v] = h;
        }
    }
}

__global__ __launch_bounds__(256, 2) void readout_kernel(
    const int* __restrict__ gid,
    const float* __restrict__ rw1, const float* __restrict__ rb1,
    const float* __restrict__ rw2, const float* __restrict__ rb2,
    float* __restrict__ out) {
    __shared__ __align__(16) float s[2402];
    for (int i = threadIdx.x; i < D * D; i += blockDim.x) s[i] = rw1[i];
    if (threadIdx.x < D) {
        s[2304 + threadIdx.x] = rb1[threadIdx.x];
        s[2352 + threadIdx.x] = rw2[threadIdx.x];
    }
    if (threadIdx.x == 0) s[2400] = rb2[0];
    __syncthreads();

    int n = blockIdx.x * 256 + threadIdx.x;
    if (n >= NN) return;

    const float4* hp = &g_h[n * 12];
    float x[D];
#pragma unroll
    for (int v = 0; v < 12; v++) {
        float4 a = hp[v];
        x[4 * v + 0] = a.x;
        x[4 * v + 1] = a.y;
        x[4 * v + 2] = a.z;
        x[4 * v + 3] = a.w;
    }

    float y = s[2400];
#pragma unroll 1
    for (int half = 0; half < 2; half++) {
        u64 acc[12];
        gemm48_half(x, acc, s + half * 24, s + 2304 + half * 24);
#pragma unroll
        for (int j = 0; j < 12; j++) {
            float2 v = unpack2(acc[j]);
            y += fmaxf(v.x, 0.f) * s[2352 + half * 24 + 2 * j];
            y += fmaxf(v.y, 0.f) * s[2352 + half * 24 + 2 * j + 1];
        }
    }

    atomicAdd(&out[gid[n]], y);
}

extern "C" void kernel_launch(void* const* d_in, const int* in_sizes, int n_in,
                              void* d_out, int out_size) {
    const int*   an   = (const int*)d_in[0];
    const int*   edge = (const int*)d_in[1];
    const int*   gid  = (const int*)d_in[2];
    const float* emb  = (const float*)d_in[3];
    const float* mw1  = (const float*)d_in[4];
    const float* mb1  = (const float*)d_in[5];
    const float* mw2  = (const float*)d_in[6];
    const float* mb2  = (const float*)d_in[7];
    const float* uw1  = (const float*)d_in[8];
    const float* ub1  = (const float*)d_in[9];
    const float* uw2  = (const float*)d_in[10];
    const float* ub2  = (const float*)d_in[11];
    const float* rw1  = (const float*)d_in[12];
    const float* rb1  = (const float*)d_in[13];
    const float* rw2  = (const float*)d_in[14];
    const float* rb2  = (const float*)d_in[15];
    float* out = (float*)d_out;

    const int edge_smem = EDGE_SMEM_FLOATS * (int)sizeof(float);  // ~71 KB
    cudaFuncSetAttribute(edge_kernel, cudaFuncAttributeMaxDynamicSharedMemorySize, edge_smem);
    cudaFuncSetAttribute(update_kernel, cudaFuncAttributeMaxDynamicSharedMemorySize, edge_smem);

    // counting sort of edges by dst (edge list constant across layers)
    zero_cnt_kernel<<<(NN + 255) / 256, 256>>>();
    hist_kernel<<<(NE + 255) / 256, 256>>>(edge);
    scan1_kernel<<<NSCAN_BLKS, SCAN_BLK>>>();
    scan2_kernel<<<1, 32>>>();
    scan3_kernel<<<(NN + 255) / 256, 256>>>();
    scatter_sort_kernel<<<(NE + 255) / 256, 256>>>(edge);

    embed_kernel<<<(NN * 12 + 255) / 256, 256>>>(an, (const float4*)emb);

    for (int l = 0; l < NCONVS; l++) {
        edge_kernel<<<NE / EPC, 128, edge_smem>>>(mw1, mb1, mw2, mb2, l);
        update_kernel<<<(NN + 255) / 256, 128, edge_smem>>>(uw1, ub1, uw2, ub2, l);
    }

    cudaMemsetAsync(out, 0, NG * sizeof(float));
    readout_kernel<<<(NN + 255) / 256, 256>>>(gid, rw1, rb1, rw2, rb2, out);
}